// round 1
// baseline (speedup 1.0000x reference)
#include <cuda_runtime.h>
#include <cstddef>
#include <math.h>

// ---------------- problem constants ----------------
constexpr int NB   = 8;
constexpr int NC   = 512;
constexpr int NSQ  = 2048;
constexpr int NSQ2 = 1024;
constexpr int NSQ4 = 512;
constexpr int NSKV = 512;
constexpr int NH   = 4;
constexpr int NHD  = 128;
constexpr float F_PS = 0.31622776601683794f;  // sqrt(0.1)
constexpr float F_S2 = 1.0f / 128.0f;          // scale^2 = 1/HD

// ---------------- scratch (device globals; no allocs allowed) ----------------
__device__ float g_tmp[NB * NC * NSQ];          // conv pre-pool buffer (32MB)
__device__ float g_x0 [NB * NC * NSQ2];         // 16MB
__device__ float g_x1 [NB * NC * NSQ4];         // 8MB
__device__ float g_qx [NB * NSQ2 * NC];         // 16MB
__device__ float g_q  [NB * NSQ2 * NC];         // 16MB
__device__ float g_k  [NB * NSKV * NC];         // 8MB
__device__ float g_v  [NB * NSKV * NC];         // 8MB
__device__ float g_x2 [NB * NH * NSQ2];
__device__ float g_y2 [NB * NH * NSKV];
__device__ float g_a0 [NB * NH * NSQ2 * NSKV];  // 64MB (pre-conv scores)
__device__ float g_a1 [NB * NH * NSQ2 * NSKV];  // 64MB (post conv / softmaxed)
__device__ float g_y  [NB * NSQ2 * NC];         // 16MB (attn @ v)

// ============================================================
// conv1d (k=3, SAME) + SiLU.  in: [B,Cin,L] (TR=false) or [B,L,Cin] (TR=true)
// out: [B,Cout,L].  BM(co)=64, BL=64, BK(ci)=16, 256 threads, 4x4/thread.
// ============================================================
template<bool TR, int L>
__global__ void __launch_bounds__(256)
k_conv1d_silu(const float* __restrict__ x, const float* __restrict__ w,
              const float* __restrict__ bias, float* __restrict__ out)
{
    __shared__ float ws[16][64][3];   // [ci][co][t]
    __shared__ float xs[16][68];      // [ci][l0-1 .. l0+64] (66 used, padded)
    const int b   = blockIdx.z;
    const int co0 = blockIdx.y * 64;
    const int l0  = blockIdx.x * 64;
    const int tid = threadIdx.x;
    const int tco = (tid >> 4) * 4;
    const int tl  = (tid & 15) * 4;
    float acc[4][4] = {};

    for (int k0 = 0; k0 < NC; k0 += 16) {
        // weights: w[co][ci][t], 64*16*3 = 3072
        for (int idx = tid; idx < 64 * 48; idx += 256) {
            int t  = idx % 3;
            int kk = (idx / 3) & 15;
            int i  = idx / 48;
            ws[kk][i][t] = w[(size_t)(co0 + i) * (NC * 3) + (size_t)(k0 + kk) * 3 + t];
        }
        // input halo tile: 16 ci x 66 positions
        for (int idx = tid; idx < 16 * 66; idx += 256) {
            int kk, j;
            if (TR) { kk = idx & 15; j = idx >> 4; }
            else    { j = idx % 66;  kk = idx / 66; }
            int gl = l0 - 1 + j;
            float v = 0.f;
            if (gl >= 0 && gl < L) {
                v = TR ? x[((size_t)b * L + gl) * NC + (k0 + kk)]
                       : x[((size_t)b * NC + (k0 + kk)) * L + gl];
            }
            xs[kk][j] = v;
        }
        __syncthreads();
        #pragma unroll
        for (int kk = 0; kk < 16; kk++) {
            float4 x4 = *reinterpret_cast<const float4*>(&xs[kk][tl]);
            float xv[6] = { x4.x, x4.y, x4.z, x4.w, xs[kk][tl + 4], xs[kk][tl + 5] };
            #pragma unroll
            for (int i = 0; i < 4; i++) {
                float a0 = ws[kk][tco + i][0];
                float a1 = ws[kk][tco + i][1];
                float a2 = ws[kk][tco + i][2];
                #pragma unroll
                for (int j = 0; j < 4; j++)
                    acc[i][j] += a0 * xv[j] + a1 * xv[j + 1] + a2 * xv[j + 2];
            }
        }
        __syncthreads();
    }
    #pragma unroll
    for (int i = 0; i < 4; i++) {
        int co = co0 + tco + i;
        float bb = bias[co];
        #pragma unroll
        for (int j = 0; j < 4; j++) {
            float v = acc[i][j] + bb;
            v = v / (1.f + __expf(-v));           // SiLU
            out[((size_t)b * NC + co) * L + (l0 + tl + j)] = v;
        }
    }
}

// ============================================================
// LayerNorm over channel dim of [B,C,L] buffer, in place.
// One thread per (b,l) column: fully coalesced (threads map to adjacent l).
// ============================================================
template<int L>
__global__ void k_layernorm_ch(float* __restrict__ buf, const float* __restrict__ g,
                               const float* __restrict__ bp)
{
    int col = blockIdx.x * blockDim.x + threadIdx.x;
    if (col >= NB * L) return;
    int b = col / L, l = col - b * L;
    float* p = buf + (size_t)b * NC * L + l;
    float s = 0.f, ss = 0.f;
    #pragma unroll 8
    for (int c = 0; c < NC; c++) {
        float v = p[(size_t)c * L];
        s += v; ss += v * v;
    }
    float mean = s * (1.f / NC);
    float var  = ss * (1.f / NC) - mean * mean;
    float inv  = rsqrtf(var + 1e-5f);
    #pragma unroll 8
    for (int c = 0; c < NC; c++) {
        float v = p[(size_t)c * L];
        p[(size_t)c * L] = (v - mean) * inv * g[c] + bp[c];
    }
}

// ============================================================
// MaxPool1d k=3 s=2 p=1 (pad = -inf): [B,C,L] -> [B,C,L/2]
// ============================================================
template<int L>
__global__ void k_maxpool(const float* __restrict__ in, float* __restrict__ out)
{
    const int LO = L / 2;
    int idx = blockIdx.x * blockDim.x + threadIdx.x;
    if (idx >= NB * NC * LO) return;
    int lo = idx % LO;
    int bc = idx / LO;
    const float* p = in + (size_t)bc * L;
    int l = 2 * lo;
    float m = p[l];
    if (l - 1 >= 0) m = fmaxf(m, p[l - 1]);
    if (l + 1 < L)  m = fmaxf(m, p[l + 1]);
    out[idx] = m;
}

// ============================================================
// qx[b,l,c] = x0[b,c,l] + x1[b,c,l/2]   (fused transpose + nearest-upsample add)
// ============================================================
__global__ void k_build_qx(const float* __restrict__ x0, const float* __restrict__ x1,
                           float* __restrict__ qx)
{
    __shared__ float s[32][33];
    const int b  = blockIdx.z;
    const int c0 = blockIdx.y * 32;
    const int l0 = blockIdx.x * 32;
    for (int i = threadIdx.y; i < 32; i += 8) {
        int c = c0 + i;
        int l = l0 + threadIdx.x;
        s[i][threadIdx.x] = x0[((size_t)b * NC + c) * NSQ2 + l]
                          + x1[((size_t)b * NC + c) * NSQ4 + (l >> 1)];
    }
    __syncthreads();
    for (int i = threadIdx.y; i < 32; i += 8) {
        int l = l0 + i;
        int c = c0 + threadIdx.x;
        qx[((size_t)b * NSQ2 + l) * NC + c] = s[threadIdx.x][i];
    }
}

// ============================================================
// Generic GEMM: out[m,n] = sum_k A[m,k] * W[n,k]  (K=N=512)
// MODE 0: plain. MODE 1: + PS*q_freqs[b, 2l+1, n%128] (S=SQ2)
// MODE 2: + PS*k_freqs[b, l, n%128] (S=SKV)
// MODE 3: + bias[n], duplicate-write rows 2l and 2l+1 of [B,SQ,C] output.
// ============================================================
template<int MODE, int S>
__global__ void __launch_bounds__(256)
k_gemm_nt(const float* __restrict__ A, const float* __restrict__ W,
          const float* __restrict__ freqs, const float* __restrict__ bias,
          float* __restrict__ out)
{
    const int K = 512, N = 512;
    __shared__ float As[16][68];
    __shared__ float Bs[16][68];
    const int m0 = blockIdx.y * 64, n0 = blockIdx.x * 64;
    const int tid = threadIdx.x;
    const int tm = (tid >> 4) * 4, tn = (tid & 15) * 4;
    float acc[4][4] = {};
    for (int k0 = 0; k0 < K; k0 += 16) {
        #pragma unroll
        for (int idx = tid; idx < 1024; idx += 256) {
            int kk = idx & 15, r = idx >> 4;
            As[kk][r] = A[(size_t)(m0 + r) * K + k0 + kk];
        }
        #pragma unroll
        for (int idx = tid; idx < 1024; idx += 256) {
            int kk = idx & 15, r = idx >> 4;
            Bs[kk][r] = W[(size_t)(n0 + r) * K + k0 + kk];
        }
        __syncthreads();
        #pragma unroll
        for (int kk = 0; kk < 16; kk++) {
            float4 a4 = *reinterpret_cast<const float4*>(&As[kk][tm]);
            float4 b4 = *reinterpret_cast<const float4*>(&Bs[kk][tn]);
            float a[4]  = { a4.x, a4.y, a4.z, a4.w };
            float bv[4] = { b4.x, b4.y, b4.z, b4.w };
            #pragma unroll
            for (int i = 0; i < 4; i++)
                #pragma unroll
                for (int j = 0; j < 4; j++)
                    acc[i][j] = fmaf(a[i], bv[j], acc[i][j]);
        }
        __syncthreads();
    }
    #pragma unroll
    for (int i = 0; i < 4; i++) {
        int m = m0 + tm + i;
        int b = m / S, l = m - b * S;
        #pragma unroll
        for (int j = 0; j < 4; j++) {
            int n = n0 + tn + j;
            float v = acc[i][j];
            if (MODE == 1)
                v += F_PS * freqs[((size_t)b * NSQ + 2 * l + 1) * NHD + (n & (NHD - 1))];
            else if (MODE == 2)
                v += F_PS * freqs[((size_t)b * S + l) * NHD + (n & (NHD - 1))];
            else if (MODE == 3)
                v += bias[n];
            if (MODE == 3) {
                out[((size_t)b * NSQ + 2 * l) * N + n]     = v;
                out[((size_t)b * NSQ + 2 * l + 1) * N + n] = v;
            } else {
                out[(size_t)m * N + n] = v;
            }
        }
    }
}

// ============================================================
// row norms: o[(b*H+h)*S + i] = S2 * sum_d x[b,i,h*128+d]^2  (warp per row)
// ============================================================
template<int S>
__global__ void k_row_norms(const float* __restrict__ x, float* __restrict__ o)
{
    int gid  = blockIdx.x * (blockDim.x / 32) + (threadIdx.x >> 5);
    int lane = threadIdx.x & 31;
    if (gid >= NB * NH * S) return;
    int b = gid / (NH * S);
    int r = gid - b * NH * S;
    int h = r / S, i = r - h * S;
    const float* p = x + ((size_t)b * S + i) * NC + h * NHD;
    float s = 0.f;
    #pragma unroll
    for (int d = lane; d < NHD; d += 32) s += p[d] * p[d];
    #pragma unroll
    for (int off = 16; off; off >>= 1) s += __shfl_xor_sync(0xffffffffu, s, off);
    if (lane == 0) o[gid] = s * F_S2;
}

// ============================================================
// attn0[bh,i,j] = -max(x2[i]+y2[j]-2*S2*(q_i . k_j), 0) / temp[h]
// ============================================================
__global__ void __launch_bounds__(256)
k_attn_scores(const float* __restrict__ q, const float* __restrict__ kmat,
              const float* __restrict__ x2, const float* __restrict__ y2,
              float* __restrict__ attn0)
{
    __shared__ float As[16][68];
    __shared__ float Bs[16][68];
    const int bh = blockIdx.z;
    const int b = bh >> 2, h = bh & 3;
    const int m0 = blockIdx.y * 64, n0 = blockIdx.x * 64;
    const int tid = threadIdx.x;
    const int tm = (tid >> 4) * 4, tn = (tid & 15) * 4;
    float acc[4][4] = {};
    const float* Ab = q    + (size_t)b * NSQ2 * NC + h * NHD;
    const float* Bb = kmat + (size_t)b * NSKV * NC + h * NHD;
    for (int k0 = 0; k0 < NHD; k0 += 16) {
        #pragma unroll
        for (int idx = tid; idx < 1024; idx += 256) {
            int kk = idx & 15, r = idx >> 4;
            As[kk][r] = Ab[(size_t)(m0 + r) * NC + k0 + kk];
        }
        #pragma unroll
        for (int idx = tid; idx < 1024; idx += 256) {
            int kk = idx & 15, r = idx >> 4;
            Bs[kk][r] = Bb[(size_t)(n0 + r) * NC + k0 + kk];
        }
        __syncthreads();
        #pragma unroll
        for (int kk = 0; kk < 16; kk++) {
            float4 a4 = *reinterpret_cast<const float4*>(&As[kk][tm]);
            float4 b4 = *reinterpret_cast<const float4*>(&Bs[kk][tn]);
            float a[4]  = { a4.x, a4.y, a4.z, a4.w };
            float bv[4] = { b4.x, b4.y, b4.z, b4.w };
            #pragma unroll
            for (int i = 0; i < 4; i++)
                #pragma unroll
                for (int j = 0; j < 4; j++)
                    acc[i][j] = fmaf(a[i], bv[j], acc[i][j]);
        }
        __syncthreads();
    }
    const float invtemp = (h == 0) ? 1.f : (h == 1) ? 0.25f : (h == 2) ? (1.f / 7.f) : 0.1f;
    #pragma unroll
    for (int i = 0; i < 4; i++) {
        int ii = m0 + tm + i;
        float xi = x2[(size_t)bh * NSQ2 + ii];
        #pragma unroll
        for (int j = 0; j < 4; j++) {
            int jj = n0 + tn + j;
            float d = xi + y2[(size_t)bh * NSKV + jj] - 2.f * F_S2 * acc[i][j];
            attn0[((size_t)bh * NSQ2 + ii) * NSKV + jj] = -fmaxf(d, 0.f) * invtemp;
        }
    }
}

// ============================================================
// Score Conv2d(H=4 -> H=4, kernel 45x5, pad 22,2) + residual + bias + mask
// Tile: 16 i x 128 j, all 4 output heads; input tile 4 x 60 x 132 in smem.
// ============================================================
constexpr int CONV_SX = 4 * 60 * 132;
constexpr int CONV_SMEM = (CONV_SX + 3600) * 4;

__global__ void __launch_bounds__(256)
k_score_conv(const float* __restrict__ attn0, const float* __restrict__ sw_g,
             const float* __restrict__ sb, const float* __restrict__ mask,
             float* __restrict__ attn1)
{
    extern __shared__ float sm[];
    float* sx = sm;             // [hi][60][132]
    float* sw = sm + CONV_SX;   // [ho][hi][45][5] = 3600
    const int b  = blockIdx.z;
    const int i0 = blockIdx.y * 16;
    const int j0 = blockIdx.x * 128;
    const int tid = threadIdx.x;

    for (int idx = tid; idx < 3600; idx += 256) sw[idx] = sw_g[idx];
    for (int idx = tid; idx < CONV_SX; idx += 256) {
        int cc = idx % 132;
        int rr = (idx / 132) % 60;
        int hi = idx / (132 * 60);
        int gi = i0 - 22 + rr;
        int gj = j0 - 2 + cc;
        float v = 0.f;
        if ((unsigned)gi < (unsigned)NSQ2 && (unsigned)gj < (unsigned)NSKV)
            v = attn0[(((size_t)b * 4 + hi) * NSQ2 + gi) * NSKV + gj];
        sx[idx] = v;
    }
    __syncthreads();

    const int il  = tid >> 4;          // 0..15
    const int jl0 = (tid & 15) * 8;    // 0..120
    float acc[4][8] = {};
    for (int hi = 0; hi < 4; hi++) {
        #pragma unroll 1
        for (int r = 0; r < 45; r++) {
            const float* row = sx + ((size_t)(hi * 60 + il + r)) * 132 + jl0;
            float4 v0 = *reinterpret_cast<const float4*>(row);
            float4 v1 = *reinterpret_cast<const float4*>(row + 4);
            float4 v2 = *reinterpret_cast<const float4*>(row + 8);
            float xv[12] = { v0.x, v0.y, v0.z, v0.w,
                             v1.x, v1.y, v1.z, v1.w,
                             v2.x, v2.y, v2.z, v2.w };
            const float* wr = sw + hi * 225 + r * 5;
            #pragma unroll
            for (int s = 0; s < 5; s++) {
                float w0 = wr[s], w1 = wr[900 + s], w2 = wr[1800 + s], w3 = wr[2700 + s];
                #pragma unroll
                for (int j = 0; j < 8; j++) {
                    float xvv = xv[j + s];
                    acc[0][j] = fmaf(w0, xvv, acc[0][j]);
                    acc[1][j] = fmaf(w1, xvv, acc[1][j]);
                    acc[2][j] = fmaf(w2, xvv, acc[2][j]);
                    acc[3][j] = fmaf(w3, xvv, acc[3][j]);
                }
            }
        }
    }
    const int gi = i0 + il;
    #pragma unroll
    for (int ho = 0; ho < 4; ho++) {
        float bb = sb[ho];
        #pragma unroll
        for (int j = 0; j < 8; j++) {
            int gj = j0 + jl0 + j;
            float base = sx[(size_t)(ho * 60 + il + 22) * 132 + (jl0 + j + 2)];
            float mk = mask[((size_t)b * NSQ2 + gi) * NSKV + gj];
            attn1[(((size_t)b * 4 + ho) * NSQ2 + gi) * NSKV + gj] = base + acc[ho][j] + bb + mk;
        }
    }
}

// ============================================================
// softmax over j (512) + prior log-fusion + renorm, in place; also writes
// the row-duplicated [B,H,SQ,SKV] attn output.  Block per row, 128 threads.
// ============================================================
__global__ void __launch_bounds__(128)
k_softmax_prior(float* __restrict__ attn, const float* __restrict__ prior,
                float* __restrict__ oattn, int write_attn)
{
    __shared__ float red[4];
    const int row = blockIdx.x;             // (b*H+h)*SQ2 + i
    const int bh = row / NSQ2;
    const int i  = row - bh * NSQ2;
    const int b  = bh >> 2;
    float* p = attn + (size_t)row * NSKV;
    const float* pr = prior + ((size_t)b * NSQ + 2 * i + 1) * NSKV;
    const int t = threadIdx.x;

    float v[4];
    #pragma unroll
    for (int j = 0; j < 4; j++) v[j] = p[t + 128 * j];

    float mx = fmaxf(fmaxf(v[0], v[1]), fmaxf(v[2], v[3]));
    #pragma unroll
    for (int off = 16; off; off >>= 1) mx = fmaxf(mx, __shfl_xor_sync(0xffffffffu, mx, off));
    if ((t & 31) == 0) red[t >> 5] = mx;
    __syncthreads();
    mx = fmaxf(fmaxf(red[0], red[1]), fmaxf(red[2], red[3]));
    __syncthreads();

    float e[4], s = 0.f;
    #pragma unroll
    for (int j = 0; j < 4; j++) { e[j] = __expf(v[j] - mx); s += e[j]; }
    #pragma unroll
    for (int off = 16; off; off >>= 1) s += __shfl_xor_sync(0xffffffffu, s, off);
    if ((t & 31) == 0) red[t >> 5] = s;
    __syncthreads();
    s = red[0] + red[1] + red[2] + red[3];
    __syncthreads();
    float inv = 1.f / s;

    float w[4], s2 = 0.f;
    #pragma unroll
    for (int j = 0; j < 4; j++) {
        w[j] = fmaxf(e[j] * inv, 1e-8f) * fmaxf(pr[t + 128 * j], 1e-8f);
        s2 += w[j];
    }
    #pragma unroll
    for (int off = 16; off; off >>= 1) s2 += __shfl_xor_sync(0xffffffffu, s2, off);
    if ((t & 31) == 0) red[t >> 5] = s2;
    __syncthreads();
    s2 = red[0] + red[1] + red[2] + red[3];
    float i2 = 1.f / (s2 + 1e-8f);

    #pragma unroll
    for (int j = 0; j < 4; j++) {
        float o = w[j] * i2;
        p[t + 128 * j] = o;
        if (write_attn) {
            size_t o0 = ((size_t)bh * NSQ + 2 * i) * NSKV + t + 128 * j;
            oattn[o0] = o;
            oattn[o0 + NSKV] = o;
        }
    }
}

// ============================================================
// y[b,i,h*128+d] = sum_j attn[bh,i,j] * v[b,j,h*128+d]
// ============================================================
__global__ void __launch_bounds__(256)
k_attn_v(const float* __restrict__ attn, const float* __restrict__ v,
         float* __restrict__ y)
{
    __shared__ float As[16][68];
    __shared__ float Bs[16][68];
    const int bh = blockIdx.z, b = bh >> 2, h = bh & 3;
    const int m0 = blockIdx.y * 64, n0 = blockIdx.x * 64;
    const int tid = threadIdx.x;
    const int tm = (tid >> 4) * 4, tn = (tid & 15) * 4;
    float acc[4][4] = {};
    const float* Ab = attn + (size_t)bh * NSQ2 * NSKV;
    const float* Bb = v + (size_t)b * NSKV * NC + h * NHD + n0;
    for (int k0 = 0; k0 < NSKV; k0 += 16) {
        #pragma unroll
        for (int idx = tid; idx < 1024; idx += 256) {
            int kk = idx & 15, r = idx >> 4;
            As[kk][r] = Ab[(size_t)(m0 + r) * NSKV + k0 + kk];
        }
        #pragma unroll
        for (int idx = tid; idx < 1024; idx += 256) {
            int nn = idx & 63, kk = idx >> 6;
            Bs[kk][nn] = Bb[(size_t)(k0 + kk) * NC + nn];
        }
        __syncthreads();
        #pragma unroll
        for (int kk = 0; kk < 16; kk++) {
            float4 a4 = *reinterpret_cast<const float4*>(&As[kk][tm]);
            float4 b4 = *reinterpret_cast<const float4*>(&Bs[kk][tn]);
            float a[4]  = { a4.x, a4.y, a4.z, a4.w };
            float bv[4] = { b4.x, b4.y, b4.z, b4.w };
            #pragma unroll
            for (int i = 0; i < 4; i++)
                #pragma unroll
                for (int j = 0; j < 4; j++)
                    acc[i][j] = fmaf(a[i], bv[j], acc[i][j]);
        }
        __syncthreads();
    }
    #pragma unroll
    for (int i = 0; i < 4; i++)
        #pragma unroll
        for (int j = 0; j < 4; j++)
            y[((size_t)b * NSQ2 + m0 + tm + i) * NC + h * NHD + n0 + tn + j] = acc[i][j];
}

// ============================================================
// host launcher
// ============================================================
extern "C" void kernel_launch(void* const* d_in, const int* in_sizes, int n_in,
                              void* d_out, int out_size)
{
    (void)in_sizes; (void)n_in;
    const float* q_x    = (const float*)d_in[0];
    const float* kv_x   = (const float*)d_in[1];
    const float* qfreq  = (const float*)d_in[2];
    const float* kfreq  = (const float*)d_in[3];
    const float* mask   = (const float*)d_in[4];
    const float* prior  = (const float*)d_in[5];
    const float* qds_cw = (const float*)d_in[6];
    const float* qds_cb = (const float*)d_in[7];
    const float* qds_g  = (const float*)d_in[8];
    const float* qds_b  = (const float*)d_in[9];
    const float* qp_cw  = (const float*)d_in[10];   // layer 0 only (layer 1 unused by ref)
    const float* qp_cb  = (const float*)d_in[11];
    const float* qp_g   = (const float*)d_in[12];
    const float* qp_b   = (const float*)d_in[13];
    const float* wq     = (const float*)d_in[14];
    const float* wk     = (const float*)d_in[15];
    const float* wv     = (const float*)d_in[16];
    const float* sw     = (const float*)d_in[17];
    const float* sb     = (const float*)d_in[18];
    const float* pw     = (const float*)d_in[19];
    const float* pb     = (const float*)d_in[20];

    float* out = (float*)d_out;
    const size_t XOUT_N = (size_t)NB * NSQ * NC;
    const size_t ATT_N  = (size_t)NB * NH * NSQ * NSKV;
    int write_attn = ((size_t)out_size >= XOUT_N + ATT_N) ? 1 : 0;
    float* out_attn = out + XOUT_N;

    void* pv;
    cudaGetSymbolAddress(&pv, g_tmp); float* tmp = (float*)pv;
    cudaGetSymbolAddress(&pv, g_x0);  float* x0  = (float*)pv;
    cudaGetSymbolAddress(&pv, g_x1);  float* x1  = (float*)pv;
    cudaGetSymbolAddress(&pv, g_qx);  float* qx  = (float*)pv;
    cudaGetSymbolAddress(&pv, g_q);   float* qb  = (float*)pv;
    cudaGetSymbolAddress(&pv, g_k);   float* kb  = (float*)pv;
    cudaGetSymbolAddress(&pv, g_v);   float* vb  = (float*)pv;
    cudaGetSymbolAddress(&pv, g_x2);  float* x2b = (float*)pv;
    cudaGetSymbolAddress(&pv, g_y2);  float* y2b = (float*)pv;
    cudaGetSymbolAddress(&pv, g_a0);  float* a0  = (float*)pv;
    cudaGetSymbolAddress(&pv, g_a1);  float* a1  = (float*)pv;
    cudaGetSymbolAddress(&pv, g_y);   float* yb  = (float*)pv;

    // ds block 1: q_x [B,Sq,C] -> x0 [B,C,Sq2]
    k_conv1d_silu<true,  NSQ ><<<dim3(NSQ  / 64, NC / 64, NB), 256>>>(q_x, qds_cw, qds_cb, tmp);
    k_layernorm_ch<NSQ ><<<(NB * NSQ  + 127) / 128, 128>>>(tmp, qds_g, qds_b);
    k_maxpool<NSQ ><<<(NB * NC * NSQ2 + 255) / 256, 256>>>(tmp, x0);

    // ds block 2 (qp layer 0): x0 -> x1 [B,C,Sq4]
    k_conv1d_silu<false, NSQ2><<<dim3(NSQ2 / 64, NC / 64, NB), 256>>>(x0, qp_cw, qp_cb, tmp);
    k_layernorm_ch<NSQ2><<<(NB * NSQ2 + 127) / 128, 128>>>(tmp, qp_g, qp_b);
    k_maxpool<NSQ2><<<(NB * NC * NSQ4 + 255) / 256, 256>>>(tmp, x1);

    // qx = transpose(x0 + upsample2(x1))
    k_build_qx<<<dim3(NSQ2 / 32, NC / 32, NB), dim3(32, 8)>>>(x0, x1, qx);

    // q/k/v projections (+freq adds)
    k_gemm_nt<1, NSQ2><<<dim3(8, NB * NSQ2 / 64), 256>>>(qx,   wq, qfreq, nullptr, qb);
    k_gemm_nt<2, NSKV><<<dim3(8, NB * NSKV / 64), 256>>>(kv_x, wk, kfreq, nullptr, kb);
    k_gemm_nt<0, NSKV><<<dim3(8, NB * NSKV / 64), 256>>>(kv_x, wv, nullptr, nullptr, vb);

    // norms + gaussian scores
    k_row_norms<NSQ2><<<NB * NH * NSQ2 / 8, 256>>>(qb, x2b);
    k_row_norms<NSKV><<<NB * NH * NSKV / 8, 256>>>(kb, y2b);
    k_attn_scores<<<dim3(NSKV / 64, NSQ2 / 64, NB * NH), 256>>>(qb, kb, x2b, y2b, a0);

    // score conv + residual + bias + mask
    cudaFuncSetAttribute(k_score_conv, cudaFuncAttributeMaxDynamicSharedMemorySize, CONV_SMEM);
    k_score_conv<<<dim3(NSKV / 128, NSQ2 / 16, NB), 256, CONV_SMEM>>>(a0, sw, sb, mask, a1);

    // softmax + prior fusion (+ write duplicated attn output)
    k_softmax_prior<<<NB * NH * NSQ2, 128>>>(a1, prior, out_attn, write_attn);

    // attn @ v, then output projection with duplicated rows
    k_attn_v<<<dim3(NHD / 64, NSQ2 / 64, NB * NH), 256>>>(a1, vb, yb);
    k_gemm_nt<3, NSQ2><<<dim3(8, NB * NSQ2 / 64), 256>>>(yb, pw, nullptr, pb, out);
}

// round 3
// speedup vs baseline: 1.7433x; 1.7433x over previous
#include <cuda_runtime.h>
#include <cuda_bf16.h>
#include <cstdint>
#include <cstddef>
#include <math.h>

// ---------------- problem constants ----------------
constexpr int NB   = 8;
constexpr int NC   = 512;
constexpr int NSQ  = 2048;
constexpr int NSQ2 = 1024;
constexpr int NSQ4 = 512;
constexpr int NSKV = 512;
constexpr int NH   = 4;
constexpr int NHD  = 128;
constexpr float F_PS = 0.31622776601683794f;  // sqrt(0.1)
constexpr float F_S2 = 1.0f / 128.0f;          // scale^2 = 1/HD

// ---------------- scratch (device globals; no allocs allowed) ----------------
__device__ float g_tmp[NB * NC * NSQ];
__device__ float g_x0 [NB * NC * NSQ2];
__device__ float g_x1 [NB * NC * NSQ4];
__device__ float g_qx [NB * NSQ2 * NC];
__device__ float g_q  [NB * NSQ2 * NC];
__device__ float g_k  [NB * NSKV * NC];
__device__ float g_v  [NB * NSKV * NC];
__device__ float g_x2 [NB * NH * NSQ2];
__device__ float g_y2 [NB * NH * NSKV];
__device__ float g_a0 [NB * NH * NSQ2 * NSKV];
__device__ float g_a1 [NB * NH * NSQ2 * NSKV];
__device__ float g_y  [NB * NSQ2 * NC];
// split-bf16 conv weights, K-order (t, ci): w'[co][t*512+ci]
__device__ __nv_bfloat16 g_whi1[NC * NC * 3];
__device__ __nv_bfloat16 g_wlo1[NC * NC * 3];
__device__ __nv_bfloat16 g_whi2[NC * NC * 3];
__device__ __nv_bfloat16 g_wlo2[NC * NC * 3];
// split-bf16 plain GEMM weights: [4][n=512][k=512]  (wq, wk, wv, proj)
__device__ __nv_bfloat16 g_pwhi[4 * NC * NC];
__device__ __nv_bfloat16 g_pwlo[4 * NC * NC];

// ============================================================
// mma.sync / ldmatrix helpers (sm_80-compatible PTX)
// ============================================================
__device__ __forceinline__ uint32_t smem_u32(const void* p) {
    uint32_t a;
    asm("{ .reg .u64 t; cvta.to.shared.u64 t, %1; cvt.u32.u64 %0, t; }" : "=r"(a) : "l"(p));
    return a;
}
__device__ __forceinline__ void ldsm_x4(uint32_t* r, uint32_t addr) {
    asm volatile("ldmatrix.sync.aligned.m8n8.x4.shared.b16 {%0,%1,%2,%3}, [%4];"
        : "=r"(r[0]), "=r"(r[1]), "=r"(r[2]), "=r"(r[3]) : "r"(addr));
}
__device__ __forceinline__ void ldsm_x2(uint32_t* r, uint32_t addr) {
    asm volatile("ldmatrix.sync.aligned.m8n8.x2.shared.b16 {%0,%1}, [%2];"
        : "=r"(r[0]), "=r"(r[1]) : "r"(addr));
}
__device__ __forceinline__ void mma_bf16(float* c, const uint32_t* a, const uint32_t* b) {
    asm volatile("mma.sync.aligned.m16n8k16.row.col.f32.bf16.bf16.f32 "
        "{%0,%1,%2,%3}, {%4,%5,%6,%7}, {%8,%9}, {%0,%1,%2,%3};"
        : "+f"(c[0]), "+f"(c[1]), "+f"(c[2]), "+f"(c[3])
        : "r"(a[0]), "r"(a[1]), "r"(a[2]), "r"(a[3]), "r"(b[0]), "r"(b[1]));
}
__device__ __forceinline__ uint32_t packhl(__nv_bfloat16 a, __nv_bfloat16 b) {
    uint16_t ua = *reinterpret_cast<uint16_t*>(&a);
    uint16_t ub = *reinterpret_cast<uint16_t*>(&b);
    return (uint32_t)ua | ((uint32_t)ub << 16);
}
// split 8 f32 into hi/lo bf16 uint4s
__device__ __forceinline__ void split8(const float* f, uint4& hi, uint4& lo) {
    __nv_bfloat16 h[8], l[8];
    #pragma unroll
    for (int i = 0; i < 8; i++) {
        h[i] = __float2bfloat16(f[i]);
        l[i] = __float2bfloat16(f[i] - __bfloat162float(h[i]));
    }
    hi = make_uint4(packhl(h[0], h[1]), packhl(h[2], h[3]), packhl(h[4], h[5]), packhl(h[6], h[7]));
    lo = make_uint4(packhl(l[0], l[1]), packhl(l[2], l[3]), packhl(l[4], l[5]), packhl(l[6], l[7]));
}

// smem layout (bytes): A 64 rows x (64+8) bf16, B 128 rows x (64+8) bf16, hi+lo
constexpr int SM_A_HI = 0;
constexpr int SM_A_LO = 9216;     // 64*144
constexpr int SM_B_HI = 18432;
constexpr int SM_B_LO = 36864;    // + 128*144
constexpr int SM_TOT  = 55296;

// compute one K-chunk of 64 (4 k16 steps), 3-term split
__device__ __forceinline__ void mma_chunk(uint32_t aHiB, uint32_t aLoB,
                                          uint32_t bHiB, uint32_t bLoB,
                                          float acc[2][4][4]) {
    #pragma unroll
    for (int k16 = 0; k16 < 4; k16++) {
        uint32_t ah[2][4], al[2][4], bh[4][2], bl[4][2];
        #pragma unroll
        for (int i = 0; i < 2; i++) {
            ldsm_x4(ah[i], aHiB + i * 2304 + k16 * 32);
            ldsm_x4(al[i], aLoB + i * 2304 + k16 * 32);
        }
        #pragma unroll
        for (int j = 0; j < 4; j++) {
            ldsm_x2(bh[j], bHiB + j * 1152 + k16 * 32);
            ldsm_x2(bl[j], bLoB + j * 1152 + k16 * 32);
        }
        #pragma unroll
        for (int i = 0; i < 2; i++)
            #pragma unroll
            for (int j = 0; j < 4; j++) {
                mma_bf16(acc[i][j], ah[i], bh[j]);
                mma_bf16(acc[i][j], al[i], bh[j]);
                mma_bf16(acc[i][j], ah[i], bl[j]);
            }
    }
}

// ============================================================
// weight prep kernels
// ============================================================
__global__ void k_prep_w(const float* __restrict__ w, __nv_bfloat16* __restrict__ whi,
                         __nv_bfloat16* __restrict__ wlo)
{
    int idx = blockIdx.x * blockDim.x + threadIdx.x;
    if (idx >= NC * NC * 3) return;
    int co = idx / (NC * 3);
    int kp = idx - co * (NC * 3);
    int t  = kp / NC;
    int ci = kp - t * NC;
    float f = w[(size_t)co * (NC * 3) + ci * 3 + t];
    __nv_bfloat16 h = __float2bfloat16(f);
    whi[idx] = h;
    wlo[idx] = __float2bfloat16(f - __bfloat162float(h));
}
__global__ void k_prep_plain(const float* __restrict__ w, __nv_bfloat16* __restrict__ whi,
                             __nv_bfloat16* __restrict__ wlo)
{
    int idx = blockIdx.x * blockDim.x + threadIdx.x;
    if (idx >= NC * NC) return;
    float f = w[idx];
    __nv_bfloat16 h = __float2bfloat16(f);
    whi[idx] = h;
    wlo[idx] = __float2bfloat16(f - __bfloat162float(h));
}

// ============================================================
// conv1d k=3 SAME as implicit GEMM on mma.sync (bf16 3-split) + bias + SiLU.
// x: [B, L, C].  out: [B, C, L].  M=64(l) x N=128(co), K=1536 (t,ci)-order.
// ============================================================
template<int L>
__global__ void __launch_bounds__(256)
k_conv_mma(const float* __restrict__ x, const __nv_bfloat16* __restrict__ whi,
           const __nv_bfloat16* __restrict__ wlo, const float* __restrict__ bias,
           float* __restrict__ out)
{
    extern __shared__ char sm[];
    const uint32_t smu = smem_u32(sm);
    const int b   = blockIdx.z;
    const int l0  = blockIdx.x * 64;
    const int co0 = blockIdx.y * 128;
    const int tid = threadIdx.x;
    const int wid = tid >> 5, lane = tid & 31;
    const int wm = wid & 1, wn = wid >> 1;

    // per-lane ldmatrix base addresses (bytes)
    const uint32_t aHiB = smu + SM_A_HI + ((wm * 32 + (lane & 15)) * 72 + (lane >> 4) * 8) * 2;
    const uint32_t aLoB = aHiB + (SM_A_LO - SM_A_HI);
    const uint32_t bHiB = smu + SM_B_HI + ((wn * 32 + (lane & 7)) * 72 + ((lane >> 3) & 1) * 8) * 2;
    const uint32_t bLoB = bHiB + (SM_B_LO - SM_B_HI);

    float acc[2][4][4] = {};
    const float* xb = x + (size_t)b * L * NC;

    const int fm = tid >> 2, fq = tid & 3;   // A fill: m row, k quad

    for (int kc = 0; kc < 24; kc++) {
        if (kc) __syncthreads();
        const int k0  = kc * 64;
        const int t   = kc >> 3;
        const int ci0 = (kc & 7) * 64;

        // ---- fill A (activations, f32 -> bf16 hi/lo) ----
        {
            int l = l0 + fm + t - 1;
            char* dst = sm + SM_A_HI + fm * 144 + fq * 32;
            if ((unsigned)l < (unsigned)L) {
                const float* src = xb + (size_t)l * NC + ci0 + fq * 16;
                #pragma unroll
                for (int c2 = 0; c2 < 2; c2++) {
                    float f[8];
                    float4 v0 = *reinterpret_cast<const float4*>(src + c2 * 8);
                    float4 v1 = *reinterpret_cast<const float4*>(src + c2 * 8 + 4);
                    f[0]=v0.x; f[1]=v0.y; f[2]=v0.z; f[3]=v0.w;
                    f[4]=v1.x; f[5]=v1.y; f[6]=v1.z; f[7]=v1.w;
                    uint4 hi, lo; split8(f, hi, lo);
                    *reinterpret_cast<uint4*>(dst + c2 * 16) = hi;
                    *reinterpret_cast<uint4*>(dst + (SM_A_LO - SM_A_HI) + c2 * 16) = lo;
                }
            } else {
                uint4 z = make_uint4(0, 0, 0, 0);
                #pragma unroll
                for (int c2 = 0; c2 < 2; c2++) {
                    *reinterpret_cast<uint4*>(dst + c2 * 16) = z;
                    *reinterpret_cast<uint4*>(dst + (SM_A_LO - SM_A_HI) + c2 * 16) = z;
                }
            }
        }
        // ---- fill B (weights, pre-split bf16) ----
        #pragma unroll
        for (int j = 0; j < 4; j++) {
            int linear = tid + j * 256;
            int n = linear >> 3, c8 = linear & 7;
            size_t so = (size_t)(co0 + n) * 1536 + k0 + c8 * 8;
            *reinterpret_cast<uint4*>(sm + SM_B_HI + n * 144 + c8 * 16) =
                *reinterpret_cast<const uint4*>(&whi[so]);
            *reinterpret_cast<uint4*>(sm + SM_B_LO + n * 144 + c8 * 16) =
                *reinterpret_cast<const uint4*>(&wlo[so]);
        }
        __syncthreads();
        mma_chunk(aHiB, aLoB, bHiB, bLoB, acc);
    }

    // ---- epilogue: transpose via smem, bias + SiLU, coalesced [B,C,L] stores ----
    __syncthreads();
    float* sd = reinterpret_cast<float*>(sm);   // [128 co][68 l]
    const int g = lane >> 2, tq = lane & 3;
    #pragma unroll
    for (int i = 0; i < 2; i++) {
        int ml = wm * 32 + i * 16 + g;
        #pragma unroll
        for (int j = 0; j < 4; j++) {
            int nl = wn * 32 + j * 8 + tq * 2;
            sd[(nl)     * 68 + ml]     = acc[i][j][0];
            sd[(nl + 1) * 68 + ml]     = acc[i][j][1];
            sd[(nl)     * 68 + ml + 8] = acc[i][j][2];
            sd[(nl + 1) * 68 + ml + 8] = acc[i][j][3];
        }
    }
    __syncthreads();
    const int n = tid >> 1, half = tid & 1;
    const int co = co0 + n;
    const float bb = bias[co];
    float* op = out + ((size_t)b * NC + co) * L + l0 + half * 32;
    #pragma unroll
    for (int v = 0; v < 32; v += 4) {
        float4 d4 = *reinterpret_cast<float4*>(&sd[n * 68 + half * 32 + v]);
        float4 o;
        float v0 = d4.x + bb, v1 = d4.y + bb, v2 = d4.z + bb, v3 = d4.w + bb;
        o.x = v0 / (1.f + __expf(-v0));
        o.y = v1 / (1.f + __expf(-v1));
        o.z = v2 / (1.f + __expf(-v2));
        o.w = v3 / (1.f + __expf(-v3));
        *reinterpret_cast<float4*>(op + v) = o;
    }
}

// ============================================================
// plain GEMM on mma.sync: out[m,n] = sum_k A[m,k]*W[n,k], K=N=512.
// MODE 0: plain. 1: +PS*qfreq. 2: +PS*kfreq. 3: +bias, dup rows.
// ============================================================
template<int MODE, int S>
__global__ void __launch_bounds__(256)
k_gemm_mma(const float* __restrict__ A, const __nv_bfloat16* __restrict__ whi,
           const __nv_bfloat16* __restrict__ wlo, const float* __restrict__ freqs,
           const float* __restrict__ bias, float* __restrict__ out)
{
    extern __shared__ char sm[];
    const uint32_t smu = smem_u32(sm);
    const int m0 = blockIdx.y * 64;
    const int n0 = blockIdx.x * 128;
    const int tid = threadIdx.x;
    const int wid = tid >> 5, lane = tid & 31;
    const int wm = wid & 1, wn = wid >> 1;

    const uint32_t aHiB = smu + SM_A_HI + ((wm * 32 + (lane & 15)) * 72 + (lane >> 4) * 8) * 2;
    const uint32_t aLoB = aHiB + (SM_A_LO - SM_A_HI);
    const uint32_t bHiB = smu + SM_B_HI + ((wn * 32 + (lane & 7)) * 72 + ((lane >> 3) & 1) * 8) * 2;
    const uint32_t bLoB = bHiB + (SM_B_LO - SM_B_HI);

    float acc[2][4][4] = {};
    const int fm = tid >> 2, fq = tid & 3;

    for (int kc = 0; kc < 8; kc++) {
        if (kc) __syncthreads();
        const int k0 = kc * 64;
        // fill A
        {
            const float* src = A + (size_t)(m0 + fm) * 512 + k0 + fq * 16;
            char* dst = sm + SM_A_HI + fm * 144 + fq * 32;
            #pragma unroll
            for (int c2 = 0; c2 < 2; c2++) {
                float f[8];
                float4 v0 = *reinterpret_cast<const float4*>(src + c2 * 8);
                float4 v1 = *reinterpret_cast<const float4*>(src + c2 * 8 + 4);
                f[0]=v0.x; f[1]=v0.y; f[2]=v0.z; f[3]=v0.w;
                f[4]=v1.x; f[5]=v1.y; f[6]=v1.z; f[7]=v1.w;
                uint4 hi, lo; split8(f, hi, lo);
                *reinterpret_cast<uint4*>(dst + c2 * 16) = hi;
                *reinterpret_cast<uint4*>(dst + (SM_A_LO - SM_A_HI) + c2 * 16) = lo;
            }
        }
        // fill B
        #pragma unroll
        for (int j = 0; j < 4; j++) {
            int linear = tid + j * 256;
            int n = linear >> 3, c8 = linear & 7;
            size_t so = (size_t)(n0 + n) * 512 + k0 + c8 * 8;
            *reinterpret_cast<uint4*>(sm + SM_B_HI + n * 144 + c8 * 16) =
                *reinterpret_cast<const uint4*>(&whi[so]);
            *reinterpret_cast<uint4*>(sm + SM_B_LO + n * 144 + c8 * 16) =
                *reinterpret_cast<const uint4*>(&wlo[so]);
        }
        __syncthreads();
        mma_chunk(aHiB, aLoB, bHiB, bLoB, acc);
    }

    // epilogue: direct float2 stores
    const int g = lane >> 2, tq = lane & 3;
    #pragma unroll
    for (int i = 0; i < 2; i++) {
        #pragma unroll
        for (int j = 0; j < 4; j++) {
            int ng = n0 + wn * 32 + j * 8 + tq * 2;
            #pragma unroll
            for (int r = 0; r < 2; r++) {
                int m = m0 + wm * 32 + i * 16 + g + r * 8;
                int bb_ = m / S, l = m - bb_ * S;
                float v0 = acc[i][j][r * 2];
                float v1 = acc[i][j][r * 2 + 1];
                if (MODE == 1) {
                    const float* fp = freqs + ((size_t)bb_ * NSQ + 2 * l + 1) * NHD;
                    v0 += F_PS * fp[ng & (NHD - 1)];
                    v1 += F_PS * fp[(ng + 1) & (NHD - 1)];
                } else if (MODE == 2) {
                    const float* fp = freqs + ((size_t)bb_ * S + l) * NHD;
                    v0 += F_PS * fp[ng & (NHD - 1)];
                    v1 += F_PS * fp[(ng + 1) & (NHD - 1)];
                } else if (MODE == 3) {
                    v0 += bias[ng];
                    v1 += bias[ng + 1];
                }
                float2 o = make_float2(v0, v1);
                if (MODE == 3) {
                    *reinterpret_cast<float2*>(out + ((size_t)bb_ * NSQ + 2 * l) * 512 + ng)     = o;
                    *reinterpret_cast<float2*>(out + ((size_t)bb_ * NSQ + 2 * l + 1) * 512 + ng) = o;
                } else {
                    *reinterpret_cast<float2*>(out + (size_t)m * 512 + ng) = o;
                }
            }
        }
    }
}

// ============================================================
// LayerNorm over channel dim of [B,C,L], in place
// ============================================================
template<int L>
__global__ void k_layernorm_ch(float* __restrict__ buf, const float* __restrict__ g,
                               const float* __restrict__ bp)
{
    int col = blockIdx.x * blockDim.x + threadIdx.x;
    if (col >= NB * L) return;
    int b = col / L, l = col - b * L;
    float* p = buf + (size_t)b * NC * L + l;
    float s = 0.f, ss = 0.f;
    #pragma unroll 8
    for (int c = 0; c < NC; c++) {
        float v = p[(size_t)c * L];
        s += v; ss += v * v;
    }
    float mean = s * (1.f / NC);
    float var  = ss * (1.f / NC) - mean * mean;
    float inv  = rsqrtf(var + 1e-5f);
    #pragma unroll 8
    for (int c = 0; c < NC; c++) {
        float v = p[(size_t)c * L];
        p[(size_t)c * L] = (v - mean) * inv * g[c] + bp[c];
    }
}

// ============================================================
// MaxPool1d k=3 s=2 p=1
// ============================================================
template<int L>
__global__ void k_maxpool(const float* __restrict__ in, float* __restrict__ out)
{
    const int LO = L / 2;
    int idx = blockIdx.x * blockDim.x + threadIdx.x;
    if (idx >= NB * NC * LO) return;
    int lo = idx % LO;
    int bc = idx / LO;
    const float* p = in + (size_t)bc * L;
    int l = 2 * lo;
    float m = p[l];
    if (l - 1 >= 0) m = fmaxf(m, p[l - 1]);
    if (l + 1 < L)  m = fmaxf(m, p[l + 1]);
    out[idx] = m;
}

// ============================================================
// transpose [B,C,L2] -> [B,L2,C]
// ============================================================
__global__ void k_transpose_cl(const float* __restrict__ in, float* __restrict__ out)
{
    __shared__ float s[32][33];
    const int b  = blockIdx.z;
    const int c0 = blockIdx.y * 32;
    const int l0 = blockIdx.x * 32;
    for (int i = threadIdx.y; i < 32; i += 8)
        s[i][threadIdx.x] = in[((size_t)b * NC + c0 + i) * NSQ2 + l0 + threadIdx.x];
    __syncthreads();
    for (int i = threadIdx.y; i < 32; i += 8)
        out[((size_t)b * NSQ2 + l0 + i) * NC + c0 + threadIdx.x] = s[threadIdx.x][i];
}

// ============================================================
// qx[b,l,c] = x0[b,c,l] + x1[b,c,l/2]
// ============================================================
__global__ void k_build_qx(const float* __restrict__ x0, const float* __restrict__ x1,
                           float* __restrict__ qx)
{
    __shared__ float s[32][33];
    const int b  = blockIdx.z;
    const int c0 = blockIdx.y * 32;
    const int l0 = blockIdx.x * 32;
    for (int i = threadIdx.y; i < 32; i += 8) {
        int c = c0 + i;
        int l = l0 + threadIdx.x;
        s[i][threadIdx.x] = x0[((size_t)b * NC + c) * NSQ2 + l]
                          + x1[((size_t)b * NC + c) * NSQ4 + (l >> 1)];
    }
    __syncthreads();
    for (int i = threadIdx.y; i < 32; i += 8) {
        int l = l0 + i;
        int c = c0 + threadIdx.x;
        qx[((size_t)b * NSQ2 + l) * NC + c] = s[threadIdx.x][i];
    }
}

// ============================================================
// row norms
// ============================================================
template<int S>
__global__ void k_row_norms(const float* __restrict__ x, float* __restrict__ o)
{
    int gid  = blockIdx.x * (blockDim.x / 32) + (threadIdx.x >> 5);
    int lane = threadIdx.x & 31;
    if (gid >= NB * NH * S) return;
    int b = gid / (NH * S);
    int r = gid - b * NH * S;
    int h = r / S, i = r - h * S;
    const float* p = x + ((size_t)b * S + i) * NC + h * NHD;
    float s = 0.f;
    #pragma unroll
    for (int d = lane; d < NHD; d += 32) s += p[d] * p[d];
    #pragma unroll
    for (int off = 16; off; off >>= 1) s += __shfl_xor_sync(0xffffffffu, s, off);
    if (lane == 0) o[gid] = s * F_S2;
}

// ============================================================
// gaussian scores (fp32 tiled GEMM)
// ============================================================
__global__ void __launch_bounds__(256)
k_attn_scores(const float* __restrict__ q, const float* __restrict__ kmat,
              const float* __restrict__ x2, const float* __restrict__ y2,
              float* __restrict__ attn0)
{
    __shared__ float As[16][68];
    __shared__ float Bs[16][68];
    const int bh = blockIdx.z;
    const int b = bh >> 2, h = bh & 3;
    const int m0 = blockIdx.y * 64, n0 = blockIdx.x * 64;
    const int tid = threadIdx.x;
    const int tm = (tid >> 4) * 4, tn = (tid & 15) * 4;
    float acc[4][4] = {};
    const float* Ab = q    + (size_t)b * NSQ2 * NC + h * NHD;
    const float* Bb = kmat + (size_t)b * NSKV * NC + h * NHD;
    for (int k0 = 0; k0 < NHD; k0 += 16) {
        #pragma unroll
        for (int idx = tid; idx < 1024; idx += 256) {
            int kk = idx & 15, r = idx >> 4;
            As[kk][r] = Ab[(size_t)(m0 + r) * NC + k0 + kk];
        }
        #pragma unroll
        for (int idx = tid; idx < 1024; idx += 256) {
            int kk = idx & 15, r = idx >> 4;
            Bs[kk][r] = Bb[(size_t)(n0 + r) * NC + k0 + kk];
        }
        __syncthreads();
        #pragma unroll
        for (int kk = 0; kk < 16; kk++) {
            float4 a4 = *reinterpret_cast<const float4*>(&As[kk][tm]);
            float4 b4 = *reinterpret_cast<const float4*>(&Bs[kk][tn]);
            float a[4]  = { a4.x, a4.y, a4.z, a4.w };
            float bv[4] = { b4.x, b4.y, b4.z, b4.w };
            #pragma unroll
            for (int i = 0; i < 4; i++)
                #pragma unroll
                for (int j = 0; j < 4; j++)
                    acc[i][j] = fmaf(a[i], bv[j], acc[i][j]);
        }
        __syncthreads();
    }
    const float invtemp = (h == 0) ? 1.f : (h == 1) ? 0.25f : (h == 2) ? (1.f / 7.f) : 0.1f;
    #pragma unroll
    for (int i = 0; i < 4; i++) {
        int ii = m0 + tm + i;
        float xi = x2[(size_t)bh * NSQ2 + ii];
        #pragma unroll
        for (int j = 0; j < 4; j++) {
            int jj = n0 + tn + j;
            float d = xi + y2[(size_t)bh * NSKV + jj] - 2.f * F_S2 * acc[i][j];
            attn0[((size_t)bh * NSQ2 + ii) * NSKV + jj] = -fmaxf(d, 0.f) * invtemp;
        }
    }
}

// ============================================================
// Score Conv2d(4->4, 45x5, pad 22,2) + residual + bias + mask
// ============================================================
constexpr int CONV_SX = 4 * 60 * 132;
constexpr int CONV_SMEM = (CONV_SX + 3600) * 4;

__global__ void __launch_bounds__(256)
k_score_conv(const float* __restrict__ attn0, const float* __restrict__ sw_g,
             const float* __restrict__ sb, const float* __restrict__ mask,
             float* __restrict__ attn1)
{
    extern __shared__ float smf[];
    float* sx = smf;
    float* sw = smf + CONV_SX;
    const int b  = blockIdx.z;
    const int i0 = blockIdx.y * 16;
    const int j0 = blockIdx.x * 128;
    const int tid = threadIdx.x;

    for (int idx = tid; idx < 3600; idx += 256) sw[idx] = sw_g[idx];
    for (int idx = tid; idx < CONV_SX; idx += 256) {
        int cc = idx % 132;
        int rr = (idx / 132) % 60;
        int hi = idx / (132 * 60);
        int gi = i0 - 22 + rr;
        int gj = j0 - 2 + cc;
        float v = 0.f;
        if ((unsigned)gi < (unsigned)NSQ2 && (unsigned)gj < (unsigned)NSKV)
            v = attn0[(((size_t)b * 4 + hi) * NSQ2 + gi) * NSKV + gj];
        sx[idx] = v;
    }
    __syncthreads();

    const int il  = tid >> 4;
    const int jl0 = (tid & 15) * 8;
    float acc[4][8] = {};
    for (int hi = 0; hi < 4; hi++) {
        #pragma unroll 1
        for (int r = 0; r < 45; r++) {
            const float* row = sx + ((size_t)(hi * 60 + il + r)) * 132 + jl0;
            float4 v0 = *reinterpret_cast<const float4*>(row);
            float4 v1 = *reinterpret_cast<const float4*>(row + 4);
            float4 v2 = *reinterpret_cast<const float4*>(row + 8);
            float xv[12] = { v0.x, v0.y, v0.z, v0.w,
                             v1.x, v1.y, v1.z, v1.w,
                             v2.x, v2.y, v2.z, v2.w };
            const float* wr = sw + hi * 225 + r * 5;
            #pragma unroll
            for (int s = 0; s < 5; s++) {
                float w0 = wr[s], w1 = wr[900 + s], w2 = wr[1800 + s], w3 = wr[2700 + s];
                #pragma unroll
                for (int j = 0; j < 8; j++) {
                    float xvv = xv[j + s];
                    acc[0][j] = fmaf(w0, xvv, acc[0][j]);
                    acc[1][j] = fmaf(w1, xvv, acc[1][j]);
                    acc[2][j] = fmaf(w2, xvv, acc[2][j]);
                    acc[3][j] = fmaf(w3, xvv, acc[3][j]);
                }
            }
        }
    }
    const int gi = i0 + il;
    #pragma unroll
    for (int ho = 0; ho < 4; ho++) {
        float bb = sb[ho];
        #pragma unroll
        for (int j = 0; j < 8; j++) {
            int gj = j0 + jl0 + j;
            float base = sx[(size_t)(ho * 60 + il + 22) * 132 + (jl0 + j + 2)];
            float mk = mask[((size_t)b * NSQ2 + gi) * NSKV + gj];
            attn1[(((size_t)b * 4 + ho) * NSQ2 + gi) * NSKV + gj] = base + acc[ho][j] + bb + mk;
        }
    }
}

// ============================================================
// softmax + prior log-fusion + renorm (+ duplicated attn output)
// ============================================================
__global__ void __launch_bounds__(128)
k_softmax_prior(float* __restrict__ attn, const float* __restrict__ prior,
                float* __restrict__ oattn, int write_attn)
{
    __shared__ float red[4];
    const int row = blockIdx.x;
    const int bh = row / NSQ2;
    const int i  = row - bh * NSQ2;
    const int b  = bh >> 2;
    float* p = attn + (size_t)row * NSKV;
    const float* pr = prior + ((size_t)b * NSQ + 2 * i + 1) * NSKV;
    const int t = threadIdx.x;

    float v[4];
    #pragma unroll
    for (int j = 0; j < 4; j++) v[j] = p[t + 128 * j];

    float mx = fmaxf(fmaxf(v[0], v[1]), fmaxf(v[2], v[3]));
    #pragma unroll
    for (int off = 16; off; off >>= 1) mx = fmaxf(mx, __shfl_xor_sync(0xffffffffu, mx, off));
    if ((t & 31) == 0) red[t >> 5] = mx;
    __syncthreads();
    mx = fmaxf(fmaxf(red[0], red[1]), fmaxf(red[2], red[3]));
    __syncthreads();

    float e[4], s = 0.f;
    #pragma unroll
    for (int j = 0; j < 4; j++) { e[j] = __expf(v[j] - mx); s += e[j]; }
    #pragma unroll
    for (int off = 16; off; off >>= 1) s += __shfl_xor_sync(0xffffffffu, s, off);
    if ((t & 31) == 0) red[t >> 5] = s;
    __syncthreads();
    s = red[0] + red[1] + red[2] + red[3];
    __syncthreads();
    float inv = 1.f / s;

    float w[4], s2 = 0.f;
    #pragma unroll
    for (int j = 0; j < 4; j++) {
        w[j] = fmaxf(e[j] * inv, 1e-8f) * fmaxf(pr[t + 128 * j], 1e-8f);
        s2 += w[j];
    }
    #pragma unroll
    for (int off = 16; off; off >>= 1) s2 += __shfl_xor_sync(0xffffffffu, s2, off);
    if ((t & 31) == 0) red[t >> 5] = s2;
    __syncthreads();
    s2 = red[0] + red[1] + red[2] + red[3];
    float i2 = 1.f / (s2 + 1e-8f);

    #pragma unroll
    for (int j = 0; j < 4; j++) {
        float o = w[j] * i2;
        p[t + 128 * j] = o;
        if (write_attn) {
            size_t o0 = ((size_t)bh * NSQ + 2 * i) * NSKV + t + 128 * j;
            oattn[o0] = o;
            oattn[o0 + NSKV] = o;
        }
    }
}

// ============================================================
// attn @ v (fp32 tiled GEMM)
// ============================================================
__global__ void __launch_bounds__(256)
k_attn_v(const float* __restrict__ attn, const float* __restrict__ v,
         float* __restrict__ y)
{
    __shared__ float As[16][68];
    __shared__ float Bs[16][68];
    const int bh = blockIdx.z, b = bh >> 2, h = bh & 3;
    const int m0 = blockIdx.y * 64, n0 = blockIdx.x * 64;
    const int tid = threadIdx.x;
    const int tm = (tid >> 4) * 4, tn = (tid & 15) * 4;
    float acc[4][4] = {};
    const float* Ab = attn + (size_t)bh * NSQ2 * NSKV;
    const float* Bb = v + (size_t)b * NSKV * NC + h * NHD + n0;
    for (int k0 = 0; k0 < NSKV; k0 += 16) {
        #pragma unroll
        for (int idx = tid; idx < 1024; idx += 256) {
            int kk = idx & 15, r = idx >> 4;
            As[kk][r] = Ab[(size_t)(m0 + r) * NSKV + k0 + kk];
        }
        #pragma unroll
        for (int idx = tid; idx < 1024; idx += 256) {
            int nn = idx & 63, kk = idx >> 6;
            Bs[kk][nn] = Bb[(size_t)(k0 + kk) * NC + nn];
        }
        __syncthreads();
        #pragma unroll
        for (int kk = 0; kk < 16; kk++) {
            float4 a4 = *reinterpret_cast<const float4*>(&As[kk][tm]);
            float4 b4 = *reinterpret_cast<const float4*>(&Bs[kk][tn]);
            float a[4]  = { a4.x, a4.y, a4.z, a4.w };
            float bv[4] = { b4.x, b4.y, b4.z, b4.w };
            #pragma unroll
            for (int i = 0; i < 4; i++)
                #pragma unroll
                for (int j = 0; j < 4; j++)
                    acc[i][j] = fmaf(a[i], bv[j], acc[i][j]);
        }
        __syncthreads();
    }
    #pragma unroll
    for (int i = 0; i < 4; i++)
        #pragma unroll
        for (int j = 0; j < 4; j++)
            y[((size_t)b * NSQ2 + m0 + tm + i) * NC + h * NHD + n0 + tn + j] = acc[i][j];
}

// ============================================================
// host launcher
// ============================================================
extern "C" void kernel_launch(void* const* d_in, const int* in_sizes, int n_in,
                              void* d_out, int out_size)
{
    (void)in_sizes; (void)n_in;
    const float* q_x    = (const float*)d_in[0];
    const float* kv_x   = (const float*)d_in[1];
    const float* qfreq  = (const float*)d_in[2];
    const float* kfreq  = (const float*)d_in[3];
    const float* mask   = (const float*)d_in[4];
    const float* prior  = (const float*)d_in[5];
    const float* qds_cw = (const float*)d_in[6];
    const float* qds_cb = (const float*)d_in[7];
    const float* qds_g  = (const float*)d_in[8];
    const float* qds_b  = (const float*)d_in[9];
    const float* qp_cw  = (const float*)d_in[10];
    const float* qp_cb  = (const float*)d_in[11];
    const float* qp_g   = (const float*)d_in[12];
    const float* qp_b   = (const float*)d_in[13];
    const float* wq     = (const float*)d_in[14];
    const float* wk     = (const float*)d_in[15];
    const float* wv     = (const float*)d_in[16];
    const float* sw     = (const float*)d_in[17];
    const float* sb     = (const float*)d_in[18];
    const float* pw     = (const float*)d_in[19];
    const float* pb     = (const float*)d_in[20];

    float* out = (float*)d_out;
    const size_t XOUT_N = (size_t)NB * NSQ * NC;
    const size_t ATT_N  = (size_t)NB * NH * NSQ * NSKV;
    int write_attn = ((size_t)out_size >= XOUT_N + ATT_N) ? 1 : 0;
    float* out_attn = out + XOUT_N;

    void* pv;
    cudaGetSymbolAddress(&pv, g_tmp); float* tmp = (float*)pv;
    cudaGetSymbolAddress(&pv, g_x0);  float* x0  = (float*)pv;
    cudaGetSymbolAddress(&pv, g_x1);  float* x1  = (float*)pv;
    cudaGetSymbolAddress(&pv, g_qx);  float* qx  = (float*)pv;
    cudaGetSymbolAddress(&pv, g_q);   float* qb  = (float*)pv;
    cudaGetSymbolAddress(&pv, g_k);   float* kb  = (float*)pv;
    cudaGetSymbolAddress(&pv, g_v);   float* vb  = (float*)pv;
    cudaGetSymbolAddress(&pv, g_x2);  float* x2b = (float*)pv;
    cudaGetSymbolAddress(&pv, g_y2);  float* y2b = (float*)pv;
    cudaGetSymbolAddress(&pv, g_a0);  float* a0  = (float*)pv;
    cudaGetSymbolAddress(&pv, g_a1);  float* a1  = (float*)pv;
    cudaGetSymbolAddress(&pv, g_y);   float* yb  = (float*)pv;
    cudaGetSymbolAddress(&pv, g_whi1); __nv_bfloat16* whi1 = (__nv_bfloat16*)pv;
    cudaGetSymbolAddress(&pv, g_wlo1); __nv_bfloat16* wlo1 = (__nv_bfloat16*)pv;
    cudaGetSymbolAddress(&pv, g_whi2); __nv_bfloat16* whi2 = (__nv_bfloat16*)pv;
    cudaGetSymbolAddress(&pv, g_wlo2); __nv_bfloat16* wlo2 = (__nv_bfloat16*)pv;
    cudaGetSymbolAddress(&pv, g_pwhi); __nv_bfloat16* pwhi = (__nv_bfloat16*)pv;
    cudaGetSymbolAddress(&pv, g_pwlo); __nv_bfloat16* pwlo = (__nv_bfloat16*)pv;

    cudaFuncSetAttribute(k_conv_mma<NSQ>,  cudaFuncAttributeMaxDynamicSharedMemorySize, SM_TOT);
    cudaFuncSetAttribute(k_conv_mma<NSQ2>, cudaFuncAttributeMaxDynamicSharedMemorySize, SM_TOT);
    cudaFuncSetAttribute(k_gemm_mma<1, NSQ2>, cudaFuncAttributeMaxDynamicSharedMemorySize, SM_TOT);
    cudaFuncSetAttribute(k_gemm_mma<2, NSKV>, cudaFuncAttributeMaxDynamicSharedMemorySize, SM_TOT);
    cudaFuncSetAttribute(k_gemm_mma<0, NSKV>, cudaFuncAttributeMaxDynamicSharedMemorySize, SM_TOT);
    cudaFuncSetAttribute(k_gemm_mma<3, NSQ2>, cudaFuncAttributeMaxDynamicSharedMemorySize, SM_TOT);
    cudaFuncSetAttribute(k_score_conv, cudaFuncAttributeMaxDynamicSharedMemorySize, CONV_SMEM);

    // weight prep (bf16 hi/lo splits)
    k_prep_w<<<(NC * NC * 3 + 255) / 256, 256>>>(qds_cw, whi1, wlo1);
    k_prep_w<<<(NC * NC * 3 + 255) / 256, 256>>>(qp_cw,  whi2, wlo2);
    k_prep_plain<<<(NC * NC + 255) / 256, 256>>>(wq, pwhi + 0 * NC * NC, pwlo + 0 * NC * NC);
    k_prep_plain<<<(NC * NC + 255) / 256, 256>>>(wk, pwhi + 1 * NC * NC, pwlo + 1 * NC * NC);
    k_prep_plain<<<(NC * NC + 255) / 256, 256>>>(wv, pwhi + 2 * NC * NC, pwlo + 2 * NC * NC);
    k_prep_plain<<<(NC * NC + 255) / 256, 256>>>(pw, pwhi + 3 * NC * NC, pwlo + 3 * NC * NC);

    // ds block 1: q_x [B,Sq,C] -> conv(mma) -> tmp [B,C,Sq] -> LN -> pool -> x0
    k_conv_mma<NSQ><<<dim3(NSQ / 64, 4, NB), 256, SM_TOT>>>(q_x, whi1, wlo1, qds_cb, tmp);
    k_layernorm_ch<NSQ ><<<(NB * NSQ  + 127) / 128, 128>>>(tmp, qds_g, qds_b);
    k_maxpool<NSQ ><<<(NB * NC * NSQ2 + 255) / 256, 256>>>(tmp, x0);

    // ds block 2: transpose x0, conv(mma), LN, pool -> x1
    k_transpose_cl<<<dim3(NSQ2 / 32, NC / 32, NB), dim3(32, 8)>>>(x0, qx);
    k_conv_mma<NSQ2><<<dim3(NSQ2 / 64, 4, NB), 256, SM_TOT>>>(qx, whi2, wlo2, qp_cb, tmp);
    k_layernorm_ch<NSQ2><<<(NB * NSQ2 + 127) / 128, 128>>>(tmp, qp_g, qp_b);
    k_maxpool<NSQ2><<<(NB * NC * NSQ4 + 255) / 256, 256>>>(tmp, x1);

    // qx = transpose(x0 + upsample2(x1))
    k_build_qx<<<dim3(NSQ2 / 32, NC / 32, NB), dim3(32, 8)>>>(x0, x1, qx);

    // q/k/v projections on mma (+freq adds)
    k_gemm_mma<1, NSQ2><<<dim3(4, NB * NSQ2 / 64), 256, SM_TOT>>>(qx,   pwhi + 0 * NC * NC, pwlo + 0 * NC * NC, qfreq, nullptr, qb);
    k_gemm_mma<2, NSKV><<<dim3(4, NB * NSKV / 64), 256, SM_TOT>>>(kv_x, pwhi + 1 * NC * NC, pwlo + 1 * NC * NC, kfreq, nullptr, kb);
    k_gemm_mma<0, NSKV><<<dim3(4, NB * NSKV / 64), 256, SM_TOT>>>(kv_x, pwhi + 2 * NC * NC, pwlo + 2 * NC * NC, nullptr, nullptr, vb);

    // norms + gaussian scores
    k_row_norms<NSQ2><<<NB * NH * NSQ2 / 8, 256>>>(qb, x2b);
    k_row_norms<NSKV><<<NB * NH * NSKV / 8, 256>>>(kb, y2b);
    k_attn_scores<<<dim3(NSKV / 64, NSQ2 / 64, NB * NH), 256>>>(qb, kb, x2b, y2b, a0);

    // score conv + residual + bias + mask
    k_score_conv<<<dim3(NSKV / 128, NSQ2 / 16, NB), 256, CONV_SMEM>>>(a0, sw, sb, mask, a1);

    // softmax + prior fusion (+ duplicated attn output)
    k_softmax_prior<<<NB * NH * NSQ2, 128>>>(a1, prior, out_attn, write_attn);

    // attn @ v, then output projection with duplicated rows (mma)
    k_attn_v<<<dim3(NHD / 64, NSQ2 / 64, NB * NH), 256>>>(a1, vb, yb);
    k_gemm_mma<3, NSQ2><<<dim3(4, NB * NSQ2 / 64), 256, SM_TOT>>>(yb, pwhi + 3 * NC * NC, pwlo + 3 * NC * NC, nullptr, pb, out);
}